// round 12
// baseline (speedup 1.0000x reference)
#include <cuda_runtime.h>

#define N_NODES    50000
#define N_EDGES    800000
#define NUM_GRAPHS 256
#define IN_DIM     128
#define HDIM       64
#define HID        256
#define BN_EPS     1e-5f

#define SCAN_BLOCKS ((N_NODES + 255) / 256)    // 196
#define GEMM_BLOCKS ((N_NODES + 63) / 64)      // 782 (64-row tiles)

// ---------------- scratch (device globals; 16B-aligned) ----------------
__device__ __align__(16) float g_ylA [N_NODES * HDIM];
__device__ __align__(16) float g_yrA [N_NODES * HDIM];
__device__ __align__(16) float g_ylB [N_NODES * HDIM];
__device__ __align__(16) float g_yrB [N_NODES * HDIM];
__device__ __align__(16) float g_h1  [N_NODES * HDIM];
__device__ __align__(16) float g_pool[NUM_GRAPHS * HDIM];
__device__ __align__(16) float g_t1  [NUM_GRAPHS * HID];
__device__ __align__(16) float g_t2  [NUM_GRAPHS * (HID/2)];
__device__ __align__(16) float g_t3  [NUM_GRAPHS * (HID/4)];
__device__ __align__(16) int   g_deg     [N_NODES];
__device__ __align__(16) int   g_rowstart[N_NODES + 1];
__device__ __align__(16) int   g_cursor  [N_NODES];
__device__ __align__(16) int   g_csr     [N_EDGES];
__device__ __align__(16) int   g_gstart  [NUM_GRAPHS + 1];
__device__ __align__(16) int   g_bsum    [SCAN_BLOCKS];
__device__ __align__(16) int   g_boff    [SCAN_BLOCKS];
__device__ int g_idx64;

__device__ __forceinline__ int load_idx(const void* p, long i) {
    return g_idx64 ? (int)((const long long*)p)[i] : ((const int*)p)[i];
}
__device__ __forceinline__ int clampi(int v, int lo, int hi) {
    return v < lo ? lo : (v > hi ? hi : v);
}
__device__ __forceinline__ const float* yl_src(int s) { return s ? g_ylB : g_ylA; }
__device__ __forceinline__ const float* yr_src(int s) { return s ? g_yrB : g_yrA; }
__device__ __forceinline__ float*       yl_dst(int s) { return s ? g_ylB : g_ylA; }
__device__ __forceinline__ float*       yr_dst(int s) { return s ? g_yrB : g_yrA; }
__device__ __forceinline__ const float* mlp_src(int sel) {
    switch (sel) { case 0: return g_pool; case 1: return g_t1;
                   case 2: return g_t2;  default: return g_t3; }
}
__device__ __forceinline__ float* mlp_dst(int sel, float* outparam) {
    switch (sel) { case 1: return g_t1; case 2: return g_t2;
                   case 3: return g_t3; default: return outparam; }
}

// ---------------- init: zero degree counters + detect index dtype ----------------
__global__ void k_init(const int* __restrict__ ei32) {
    if (blockIdx.x < SCAN_BLOCKS) {
        int i = blockIdx.x * 256 + threadIdx.x;
        if (i < N_NODES) g_deg[i] = 0;
    } else {
        __shared__ int s_ok;
        if (threadIdx.x == 0) s_ok = 1;
        __syncthreads();
        int k = threadIdx.x;
        int bad = (ei32[2 * k + 1] != 0) | (ei32[2 * (100000 + k) + 1] != 0);
        if (bad) s_ok = 0;
        __syncthreads();
        if (threadIdx.x == 0) g_idx64 = s_ok;
    }
}

__global__ void k_count(const void* __restrict__ ei) {
    int e = blockIdx.x * blockDim.x + threadIdx.x;
    if (e >= N_EDGES) return;
    int d = clampi(load_idx(ei, (long)N_EDGES + e), 0, N_NODES - 1);
    atomicAdd(&g_deg[d], 1);
}

// ---------------- multi-block scan ----------------
__global__ __launch_bounds__(256) void k_scanA() {
    __shared__ int s[256];
    int node = blockIdx.x * 256 + threadIdx.x;
    int d = (node < N_NODES) ? g_deg[node] : 0;
    s[threadIdx.x] = d; __syncthreads();
    #pragma unroll
    for (int off = 128; off > 0; off >>= 1) {
        if (threadIdx.x < off) s[threadIdx.x] += s[threadIdx.x + off];
        __syncthreads();
    }
    if (threadIdx.x == 0) g_bsum[blockIdx.x] = s[0];
}
__global__ __launch_bounds__(256) void k_scanB() {
    __shared__ int s[256];
    int t = threadIdx.x;
    int v = (t < SCAN_BLOCKS) ? g_bsum[t] : 0;
    s[t] = v; __syncthreads();
    #pragma unroll
    for (int off = 1; off < 256; off <<= 1) {
        int u = (t >= off) ? s[t - off] : 0;
        __syncthreads();
        s[t] += u;
        __syncthreads();
    }
    if (t < SCAN_BLOCKS) g_boff[t] = s[t] - v;
    if (t == 255) g_rowstart[N_NODES] = s[255];
}
__global__ __launch_bounds__(256) void k_scanC_gbounds(const void* __restrict__ batch) {
    if (blockIdx.x >= SCAN_BLOCKS) {
        int g = (blockIdx.x - SCAN_BLOCKS) * 256 + threadIdx.x;
        if (g > NUM_GRAPHS) return;
        if (g == NUM_GRAPHS) { g_gstart[g] = N_NODES; return; }
        int lo = 0, hi = N_NODES;
        while (lo < hi) {
            int mid = (lo + hi) >> 1;
            if (load_idx(batch, mid) < g) lo = mid + 1; else hi = mid;
        }
        g_gstart[g] = lo;
        return;
    }
    __shared__ int s[256];
    int t = threadIdx.x;
    int node = blockIdx.x * 256 + t;
    int d = (node < N_NODES) ? g_deg[node] : 0;
    s[t] = d; __syncthreads();
    #pragma unroll
    for (int off = 1; off < 256; off <<= 1) {
        int u = (t >= off) ? s[t - off] : 0;
        __syncthreads();
        s[t] += u;
        __syncthreads();
    }
    if (node < N_NODES) {
        int r = g_boff[blockIdx.x] + s[t] - d;
        g_rowstart[node] = r;
        g_cursor[node]   = r;
    }
}

__global__ void k_fill(const void* __restrict__ ei) {
    int e = blockIdx.x * blockDim.x + threadIdx.x;
    if (e >= N_EDGES) return;
    int s = clampi(load_idx(ei, e),                 0, N_NODES - 1);
    int d = clampi(load_idx(ei, (long)N_EDGES + e), 0, N_NODES - 1);
    int slot = atomicAdd(&g_cursor[d], 1);
    if (slot < N_EDGES) g_csr[slot] = s;
}

// ---------------- layer-1 dual GEMM from x: 64 rows x 64 cols, 8x4x2 / thread ----------------
__global__ __launch_bounds__(128) void k_gemm1(
    const float* __restrict__ X,
    const float* __restrict__ Wl, const float* __restrict__ Wr)
{
    __shared__ float Xs[64][33];
    __shared__ float Wls[32][64];
    __shared__ float Wrs[32][64];

    const int tid  = threadIdx.x;
    const int rowg = tid >> 4;
    const int colg = tid & 15;
    const int row0 = blockIdx.x * 64;

    float accl[8][4] = {{0.f}}, accr[8][4] = {{0.f}};

    for (int c = 0; c < IN_DIM / 32; c++) {
        #pragma unroll
        for (int i = 0; i < 4; i++) {
            int f  = tid + i * 128;
            int r  = f >> 3;
            int c4 = f & 7;
            float4 v = make_float4(0.f, 0.f, 0.f, 0.f);
            if (row0 + r < N_NODES)
                v = *(const float4*)(X + (size_t)(row0 + r) * IN_DIM + c * 32 + c4 * 4);
            Xs[r][c4*4+0] = v.x; Xs[r][c4*4+1] = v.y;
            Xs[r][c4*4+2] = v.z; Xs[r][c4*4+3] = v.w;
        }
        #pragma unroll
        for (int i = 0; i < 4; i++) {
            int f  = tid + i * 128;
            int k  = f >> 4;
            int c4 = f & 15;
            ((float4*)Wls)[k*16 + c4] = *(const float4*)(Wl + (size_t)(c*32 + k) * 64 + c4 * 4);
            ((float4*)Wrs)[k*16 + c4] = *(const float4*)(Wr + (size_t)(c*32 + k) * 64 + c4 * 4);
        }
        __syncthreads();
        #pragma unroll 2
        for (int k = 0; k < 32; k++) {
            float4 wl = ((const float4*)Wls)[k*16 + colg];
            float4 wr = ((const float4*)Wrs)[k*16 + colg];
            #pragma unroll
            for (int i = 0; i < 8; i++) {
                float xv = Xs[rowg*8 + i][k];
                accl[i][0] += xv * wl.x; accl[i][1] += xv * wl.y;
                accl[i][2] += xv * wl.z; accl[i][3] += xv * wl.w;
                accr[i][0] += xv * wr.x; accr[i][1] += xv * wr.y;
                accr[i][2] += xv * wr.z; accr[i][3] += xv * wr.w;
            }
        }
        __syncthreads();
    }

    #pragma unroll
    for (int i = 0; i < 8; i++) {
        int r = row0 + rowg*8 + i;
        if (r < N_NODES) {
            *(float4*)(g_ylA + (size_t)r * 64 + colg * 4) =
                make_float4(accl[i][0], accl[i][1], accl[i][2], accl[i][3]);
            *(float4*)(g_yrA + (size_t)r * 64 + colg * 4) =
                make_float4(accr[i][0], accr[i][1], accr[i][2], accr[i][3]);
        }
    }
}

// ---------------- fused aggregate(prev layer) + dual GEMM(this layer) ----------------
// Block owns 64 rows. Phase 1: h[v] = mean gather(yl_src) + bl + yr_src[v] -> smem Hs.
// Phase 2: (yl_dst, yr_dst) = Hs @ (Wl | Wr). K = 64.
__global__ __launch_bounds__(128) void k_agg_gemm(
    const float* __restrict__ bl, int srcsel, int dstsel,
    const float* __restrict__ Wl, const float* __restrict__ Wr)
{
    __shared__ float Hs[64][68];     // row stride 68 floats (16B-aligned, odd float4 count)
    __shared__ float Wls[32][64];
    __shared__ float Wrs[32][64];

    const float* __restrict__ yls = yl_src(srcsel);
    const float* __restrict__ yrs = yr_src(srcsel);
    float* __restrict__ yld = yl_dst(dstsel);
    float* __restrict__ yrd = yr_dst(dstsel);

    const int tid  = threadIdx.x;
    const int row0 = blockIdx.x * 64;
    const int grp  = tid >> 4;       // 0..7 (16-lane groups)
    const int l16  = tid & 15;
    const int c4   = l16 << 2;

    // ---- phase 1: aggregate 8 nodes per group
    float4 bb = *(const float4*)(bl + c4);
    #pragma unroll
    for (int ii = 0; ii < 8; ii++) {
        int v = row0 + grp * 8 + ii;
        float4 acc = make_float4(0.f, 0.f, 0.f, 0.f);
        if (v < N_NODES) {
            const int start = g_rowstart[v];
            const int end   = g_rowstart[v + 1];
            int i = start;
            for (; i + 4 <= end; i += 4) {
                int s0 = g_csr[i], s1 = g_csr[i+1], s2 = g_csr[i+2], s3 = g_csr[i+3];
                float4 a0 = *(const float4*)(yls + (size_t)s0 * 64 + c4);
                float4 a1 = *(const float4*)(yls + (size_t)s1 * 64 + c4);
                float4 a2 = *(const float4*)(yls + (size_t)s2 * 64 + c4);
                float4 a3 = *(const float4*)(yls + (size_t)s3 * 64 + c4);
                acc.x += a0.x + a1.x + a2.x + a3.x;
                acc.y += a0.y + a1.y + a2.y + a3.y;
                acc.z += a0.z + a1.z + a2.z + a3.z;
                acc.w += a0.w + a1.w + a2.w + a3.w;
            }
            for (; i < end; i++) {
                int s = g_csr[i];
                float4 a = *(const float4*)(yls + (size_t)s * 64 + c4);
                acc.x += a.x; acc.y += a.y; acc.z += a.z; acc.w += a.w;
            }
            float inv = 1.0f / fmaxf((float)(end - start), 1.0f);
            float4 r = *(const float4*)(yrs + (size_t)v * 64 + c4);
            acc = make_float4(acc.x * inv + bb.x + r.x,
                              acc.y * inv + bb.y + r.y,
                              acc.z * inv + bb.z + r.z,
                              acc.w * inv + bb.w + r.w);
        }
        *(float4*)&Hs[grp * 8 + ii][c4] = acc;
    }

    // ---- phase 2: dual GEMM from Hs (K = 64, two 32-chunks for W staging)
    const int rowg = tid >> 4;
    const int colg = tid & 15;
    float accl[8][4] = {{0.f}}, accr[8][4] = {{0.f}};

    #pragma unroll
    for (int c = 0; c < 2; c++) {
        #pragma unroll
        for (int i = 0; i < 4; i++) {
            int f  = tid + i * 128;
            int k  = f >> 4;
            int cc = f & 15;
            ((float4*)Wls)[k*16 + cc] = *(const float4*)(Wl + (size_t)(c*32 + k) * 64 + cc * 4);
            ((float4*)Wrs)[k*16 + cc] = *(const float4*)(Wr + (size_t)(c*32 + k) * 64 + cc * 4);
        }
        __syncthreads();   // first iter: also covers Hs writes
        #pragma unroll 2
        for (int k = 0; k < 32; k++) {
            float4 wl = ((const float4*)Wls)[k*16 + colg];
            float4 wr = ((const float4*)Wrs)[k*16 + colg];
            #pragma unroll
            for (int i = 0; i < 8; i++) {
                float xv = Hs[rowg*8 + i][c*32 + k];
                accl[i][0] += xv * wl.x; accl[i][1] += xv * wl.y;
                accl[i][2] += xv * wl.z; accl[i][3] += xv * wl.w;
                accr[i][0] += xv * wr.x; accr[i][1] += xv * wr.y;
                accr[i][2] += xv * wr.z; accr[i][3] += xv * wr.w;
            }
        }
        __syncthreads();
    }

    #pragma unroll
    for (int i = 0; i < 8; i++) {
        int r = row0 + rowg*8 + i;
        if (r < N_NODES) {
            *(float4*)(yld + (size_t)r * 64 + colg * 4) =
                make_float4(accl[i][0], accl[i][1], accl[i][2], accl[i][3]);
            *(float4*)(yrd + (size_t)r * 64 + colg * 4) =
                make_float4(accr[i][0], accr[i][1], accr[i][2], accr[i][3]);
        }
    }
}

// ---------------- final aggregate (layer 3) -> g_h1 ----------------
__global__ void k_aggregate_final(const float* __restrict__ bl, int srcsel) {
    int tid = blockIdx.x * blockDim.x + threadIdx.x;
    if (tid >= N_NODES * 16) return;
    const float* __restrict__ yls = yl_src(srcsel);
    const float* __restrict__ yrs = yr_src(srcsel);
    const int v  = tid >> 4;
    const int c4 = (tid & 15) << 2;

    const int start = g_rowstart[v];
    const int end   = g_rowstart[v + 1];

    float4 acc = make_float4(0.f, 0.f, 0.f, 0.f);
    int i = start;
    for (; i + 4 <= end; i += 4) {
        int s0 = g_csr[i], s1 = g_csr[i+1], s2 = g_csr[i+2], s3 = g_csr[i+3];
        float4 a0 = *(const float4*)(yls + (size_t)s0 * 64 + c4);
        float4 a1 = *(const float4*)(yls + (size_t)s1 * 64 + c4);
        float4 a2 = *(const float4*)(yls + (size_t)s2 * 64 + c4);
        float4 a3 = *(const float4*)(yls + (size_t)s3 * 64 + c4);
        acc.x += a0.x + a1.x + a2.x + a3.x;
        acc.y += a0.y + a1.y + a2.y + a3.y;
        acc.z += a0.z + a1.z + a2.z + a3.z;
        acc.w += a0.w + a1.w + a2.w + a3.w;
    }
    for (; i < end; i++) {
        int s = g_csr[i];
        float4 a = *(const float4*)(yls + (size_t)s * 64 + c4);
        acc.x += a.x; acc.y += a.y; acc.z += a.z; acc.w += a.w;
    }

    float inv = 1.0f / fmaxf((float)(end - start), 1.0f);
    float4 r = *(const float4*)(yrs + (size_t)v * 64 + c4);
    float4 b = *(const float4*)(bl + c4);
    float4 o = make_float4(acc.x * inv + b.x + r.x,
                           acc.y * inv + b.y + r.y,
                           acc.z * inv + b.z + r.z,
                           acc.w * inv + b.w + r.w);
    *(float4*)(g_h1 + (size_t)v * 64 + c4) = o;
}

// ---------------- contiguous-segment pool ----------------
__global__ __launch_bounds__(256) void k_pool() {
    const int g = blockIdx.x;
    const int start = g_gstart[g], end = g_gstart[g + 1];
    const int col = threadIdx.x & 63;
    const int rg  = threadIdx.x >> 6;
    float acc = 0.f;
    for (int v = start + rg; v < end; v += 4)
        acc += g_h1[(size_t)v * 64 + col];
    __shared__ float s[4][64];
    s[rg][col] = acc; __syncthreads();
    if (rg == 0)
        g_pool[(size_t)g * 64 + col] = s[0][col] + s[1][col] + s[2][col] + s[3][col];
}

// ---------------- fused head layer: GEMM + (BN + tanh) ----------------
__global__ __launch_bounds__(256) void k_head(
    int asel, const float* __restrict__ W, const float* __restrict__ bias,
    const float* __restrict__ gm, const float* __restrict__ bt,
    int csel, float* outparam, int K, int Nc, int divide, int do_bn)
{
    __shared__ float s_w[256];
    __shared__ float red[256];
    const float* __restrict__ A = mlp_src(asel);
    float* __restrict__ C = mlp_dst(csel, outparam);
    const int n = blockIdx.x;
    const int m = threadIdx.x;

    for (int k = m; k < K; k += 256) s_w[k] = W[(size_t)k * Nc + n];
    __syncthreads();

    float scale = divide ? (1.0f / fmaxf((float)(g_gstart[m + 1] - g_gstart[m]), 1.0f)) : 1.0f;
    float dot = 0.f;
    for (int k = 0; k < K; k++)
        dot += A[(size_t)m * K + k] * s_w[k];
    float acc = bias[n] + scale * dot;

    if (do_bn) {
        red[m] = acc; __syncthreads();
        for (int s = 128; s > 0; s >>= 1) { if (m < s) red[m] += red[m + s]; __syncthreads(); }
        float mean = red[0] * (1.0f / NUM_GRAPHS);
        __syncthreads();
        float d = acc - mean;
        red[m] = d * d; __syncthreads();
        for (int s = 128; s > 0; s >>= 1) { if (m < s) red[m] += red[m + s]; __syncthreads(); }
        float var = red[0] * (1.0f / NUM_GRAPHS);
        acc = tanhf(d * rsqrtf(var + BN_EPS) * gm[n] + bt[n]);
    }
    C[(size_t)m * Nc + n] = acc;
}

extern "C" void kernel_launch(void* const* d_in, const int* in_sizes, int n_in,
                              void* d_out, int out_size) {
    const float* x     = (const float*)d_in[0];
    const void*  ei    = d_in[1];
    const void*  batch = d_in[2];
    const float* W1l = (const float*)d_in[3];
    const float* b1l = (const float*)d_in[4];
    const float* W1r = (const float*)d_in[5];
    const float* W2l = (const float*)d_in[6];
    const float* b2l = (const float*)d_in[7];
    const float* W2r = (const float*)d_in[8];
    const float* W3l = (const float*)d_in[9];
    const float* b3l = (const float*)d_in[10];
    const float* W3r = (const float*)d_in[11];
    const float* lin1_w = (const float*)d_in[12];
    const float* lin1_b = (const float*)d_in[13];
    const float* g1  = (const float*)d_in[14];
    const float* be1 = (const float*)d_in[15];
    const float* lin2_w = (const float*)d_in[16];
    const float* lin2_b = (const float*)d_in[17];
    const float* g2  = (const float*)d_in[18];
    const float* be2 = (const float*)d_in[19];
    const float* lin3_w = (const float*)d_in[20];
    const float* lin3_b = (const float*)d_in[21];
    const float* g3  = (const float*)d_in[22];
    const float* be3 = (const float*)d_in[23];
    const float* lin4_w = (const float*)d_in[24];
    const float* lin4_b = (const float*)d_in[25];
    float* out = (float*)d_out;

    const int T = 256;
    const int edge_grid   = (N_EDGES + T - 1) / T;
    const int node16_grid = (N_NODES * 16 + T - 1) / T;

    // fork-join: CSR build (side stream) overlaps layer-1 GEMM (main stream)
    cudaStream_t s2 = 0;
    cudaEvent_t  e0 = 0, e1 = 0;
    bool forked = true;
    if (cudaStreamCreateWithFlags(&s2, cudaStreamNonBlocking) != cudaSuccess) forked = false;
    if (forked && cudaEventCreateWithFlags(&e0, cudaEventDisableTiming) != cudaSuccess) forked = false;
    if (forked && cudaEventCreateWithFlags(&e1, cudaEventDisableTiming) != cudaSuccess) forked = false;

    k_init<<<SCAN_BLOCKS + 1, 256>>>((const int*)ei);

    if (forked && cudaEventRecord(e0, 0) != cudaSuccess) forked = false;
    if (forked && cudaStreamWaitEvent(s2, e0, 0) != cudaSuccess) forked = false;
    cudaStream_t cs = forked ? s2 : 0;

    k_count        <<<edge_grid, T, 0, cs>>>(ei);
    k_scanA        <<<SCAN_BLOCKS, 256, 0, cs>>>();
    k_scanB        <<<1, 256, 0, cs>>>();
    k_scanC_gbounds<<<SCAN_BLOCKS + 2, 256, 0, cs>>>(batch);
    k_fill         <<<edge_grid, T, 0, cs>>>(ei);
    if (forked) forked = (cudaEventRecord(e1, s2) == cudaSuccess);

    // main stream: layer-1 dual GEMM overlaps CSR build
    k_gemm1<<<GEMM_BLOCKS, 128>>>(x, W1l, W1r);
    if (forked) cudaStreamWaitEvent(0, e1, 0);

    // --- layer 2: fused aggregate(1) + GEMM(2):  A -> B
    k_agg_gemm<<<GEMM_BLOCKS, 128>>>(b1l, 0, 1, W2l, W2r);
    // --- layer 3: fused aggregate(2) + GEMM(3):  B -> A
    k_agg_gemm<<<GEMM_BLOCKS, 128>>>(b2l, 1, 0, W3l, W3r);
    // --- final aggregate: A -> h
    k_aggregate_final<<<node16_grid, T>>>(b3l, 0);

    // --- pool + head
    k_pool<<<NUM_GRAPHS, 256>>>();
    k_head<<<HID,   256>>>(0, lin1_w, lin1_b, g1, be1, 1, nullptr, HDIM,  HID,   1, 1);
    k_head<<<HID/2, 256>>>(1, lin2_w, lin2_b, g2, be2, 2, nullptr, HID,   HID/2, 0, 1);
    k_head<<<HID/4, 256>>>(2, lin3_w, lin3_b, g3, be3, 3, nullptr, HID/2, HID/4, 0, 1);
    k_head<<<10,    256>>>(3, lin4_w, lin4_b, nullptr, nullptr, 0, out, HID/4, 10, 0, 0);

    if (e0) cudaEventDestroy(e0);
    if (e1) cudaEventDestroy(e1);
    if (s2) cudaStreamDestroy(s2);
}